// round 5
// baseline (speedup 1.0000x reference)
#include <cuda_runtime.h>
#include <math.h>

#define N_LI 8192
#define N_RA 2048
#define N_Q  (N_LI + N_RA)
#define M_PTS 2048
#define GRIDW 513
#define TSH 5                   // 32-wide tiles
#define TILES 256
#define SEGS 8
#define SEGQ (N_Q / SEGS)       // 1280 queries per binning segment
#define SEGCAP 96               // per (tile, segment) cap; mean ~5
#define SLOWCAP 64              // per-segment wrapped-query cap; mean ~5
#define SLOW_BLOCKS 4
#define CTCAP 768               // per-tile filtered candidate cap (typ ~65-250)
#define TWO_R_SLACK 47.6691f    // 2 * 16.5*sqrt(2) + 1.0 slack

// device-global scratch (all entries re-written or count-guarded every launch)
__device__ float4 g_cand[M_PTS];            // all dynamic candidates (slow path / overflow)
__device__ int    g_ccnt;
__device__ float4 g_tc[TILES][CTCAP];       // per-tile filtered candidates
__device__ int    g_tcnt[TILES];
__device__ int2   g_qbin[TILES][SEGS][SEGCAP];  // {q, x | y<<16}
__device__ int    g_qcnt[TILES][SEGS];
__device__ int2   g_slow[SEGS][SLOWCAP];
__device__ int    g_scnt[SEGS];

// ---------------- K1: parallel prep ----------------
//   blocks [0,8):    bin queries of segment b into per-tile lists (coords packed)
//   block  8:        compact all dynamic candidates -> g_cand
//   blocks [9,265):  tile t: Umin scan -> thr -> filtered candidate list g_tc[t]
__global__ __launch_bounds__(256, 4) void k1_prep(
    const int* __restrict__ li, const int* __restrict__ ra,
    const float* __restrict__ pts, const int* __restrict__ vox)
{
    const int b = blockIdx.x, tid = threadIdx.x, lane = tid & 31;
    const unsigned FULL = 0xffffffffu;

    if (b < SEGS) {
        // ---- query binning ----
        __shared__ int s_qc[TILES];
        __shared__ int s_sc;
        if (tid < TILES) s_qc[tid] = 0;
        if (tid == 0) s_sc = 0;
        __syncthreads();
        #pragma unroll
        for (int it = 0; it < SEGQ / 256; it++) {
            int q = b * SEGQ + it * 256 + tid;
            int x, y;
            if (q < N_LI) { x = li[2 * q];             y = li[2 * q + 1]; }
            else          { int r = q - N_LI; x = ra[2 * r]; y = ra[2 * r + 1]; }
            int2 e = make_int2(q, x | (y << 16));
            if (x == 0 || y == 0) {                  // wrap risk -> slow list
                int idx = atomicAdd(&s_sc, 1);
                if (idx < SLOWCAP) g_slow[b][idx] = e;
            } else {
                int t = ((y >> TSH) << 4) | (x >> TSH);
                int idx = atomicAdd(&s_qc[t], 1);
                if (idx < SEGCAP) g_qbin[t][b][idx] = e;
            }
        }
        __syncthreads();
        if (tid < TILES) g_qcnt[tid][b] = min(s_qc[tid], SEGCAP);
        if (tid == 0) g_scnt[b] = min(s_sc, SLOWCAP);
    } else if (b == SEGS) {
        // ---- full candidate compaction (slow path + overflow fallback) ----
        __shared__ int s_cc;
        if (tid == 0) s_cc = 0;
        __syncthreads();
        #pragma unroll
        for (int it = 0; it < M_PTS / 256; it++) {
            int i = it * 256 + tid;
            bool pass = fabsf(pts[i * 5 + 4]) > 0.1f;
            unsigned m = __ballot_sync(FULL, pass);
            int base;
            if (lane == 0) base = atomicAdd(&s_cc, __popc(m));
            base = __shfl_sync(FULL, base, 0);
            if (pass) {
                float px = (float)vox[i * 3 + 1];
                float py = (float)vox[i * 3 + 2];
                g_cand[base + __popc(m & ((1u << lane) - 1u))] =
                    make_float4(px, py, fmaf(px, px, py * py), 0.0f);
            }
        }
        __syncthreads();
        if (tid == 0) g_ccnt = s_cc;
    } else {
        // ---- per-tile threshold + filtered candidate list ----
        const int t = b - SEGS - 1;
        const float refx = (float)((t & 15) << TSH) + 15.5f;
        const float refy = (float)((t >> 4) << TSH) + 15.5f;
        __shared__ float s_m[8];
        __shared__ float s_thr;
        __shared__ int   s_cc2;
        float mv = 3.0e38f;
        #pragma unroll
        for (int it = 0; it < M_PTS / 256; it++) {
            int i = it * 256 + tid;
            if (fabsf(pts[i * 5 + 4]) > 0.1f) {
                float dx = (float)vox[i * 3 + 1] - refx;
                float dy = (float)vox[i * 3 + 2] - refy;
                mv = fminf(mv, fmaf(dx, dx, dy * dy));
            }
        }
        #pragma unroll
        for (int o = 16; o; o >>= 1) mv = fminf(mv, __shfl_xor_sync(FULL, mv, o));
        if (lane == 0) s_m[tid >> 5] = mv;
        if (tid == 0) s_cc2 = 0;
        __syncthreads();
        if (tid == 0) {
            float m = s_m[0];
            #pragma unroll
            for (int i = 1; i < 8; i++) m = fminf(m, s_m[i]);
            float u = sqrtf(m) + TWO_R_SLACK;   // keep iff d(ref,c) <= sqrt(Umin)+2R+1
            s_thr = u * u;
        }
        __syncthreads();
        const float thr = s_thr;
        #pragma unroll
        for (int it = 0; it < M_PTS / 256; it++) {   // L1-hot second scan
            int i = it * 256 + tid;
            bool keep = false;
            float px = 0.f, py = 0.f;
            if (fabsf(pts[i * 5 + 4]) > 0.1f) {
                px = (float)vox[i * 3 + 1];
                py = (float)vox[i * 3 + 2];
                float dx = px - refx, dy = py - refy;
                keep = fmaf(dx, dx, dy * dy) <= thr;
            }
            unsigned m = __ballot_sync(FULL, keep);
            int base;
            if (lane == 0) base = atomicAdd(&s_cc2, __popc(m));
            base = __shfl_sync(FULL, base, 0);
            if (keep) {
                int idx = base + __popc(m & ((1u << lane) - 1u));
                if (idx < CTCAP)
                    g_tc[t][idx] = make_float4(px, py, fmaf(px, px, py * py), 0.0f);
            }
        }
        __syncthreads();
        if (tid == 0) g_tcnt[t] = s_cc2;   // may exceed CTCAP -> k2 falls back
    }
}

// ---------------- K2: 8-sliced eval (+ slow path) ----------------
__global__ __launch_bounds__(512, 2) void k2_main(float* __restrict__ out)
{
    const int b = blockIdx.x, tid = threadIdx.x, lane = tid & 31;
    const unsigned FULL = 0xffffffffu;
    const int cc = g_ccnt;
    const bool active = cc > 1;             // reference: use = sum(dy_mask) > 1

    if (b < TILES) {
        __shared__ int s_off[SEGS + 1];
        if (tid < SEGS) s_off[tid + 1] = g_qcnt[b][tid];   // parallel load
        if (tid == 0) s_off[0] = 0;
        __syncthreads();
        if (tid == 0) {
            int a = 0;
            #pragma unroll
            for (int i = 0; i < SEGS; i++) { a += s_off[i + 1]; s_off[i + 1] = a; }
        }
        __syncthreads();
        const int qn = s_off[SEGS];
        if (qn == 0) return;

        int cn = g_tcnt[b];
        const float4* __restrict__ cp = g_tc[b];
        if (cn > CTCAP) { cp = g_cand; cn = cc; }   // overflow fallback (exact superset)
        if (!active) cn = 0;

        const int s = tid & 7;              // candidate slice
        const int qslot = tid >> 3;         // 64 queries per pass
        for (int q0 = 0; q0 < qn; q0 += 64) {
            const int qi = q0 + qslot;
            const bool have = qi < qn;
            int q = 0; unsigned xy = 0;
            if (have) {
                int seg = 0;
                #pragma unroll
                for (int i = 1; i < SEGS; i++) if (qi >= s_off[i]) seg = i;
                int2 e = g_qbin[b][seg][qi - s_off[seg]];
                q = e.x; xy = (unsigned)e.y;
            }
            const int x = (int)(xy & 0xffffu), y = (int)(xy >> 16);
            // INDEX_SHIFT: dim0 {0,-1,+1} (a=j%3), dim1 {0,+1,-1} (b=j/3); no wrap here
            const float xa0 = (float)x, xa1 = (float)(x - 1), xa2 = (float)(x + 1);
            const float yb0 = (float)y, yb1 = (float)(y + 1), yb2 = (float)(y - 1);
            const float n2x0 = -2.0f * xa0, n2x1 = -2.0f * xa1, n2x2 = -2.0f * xa2;
            const float n2y0 = -2.0f * yb0, n2y1 = -2.0f * yb1, n2y2 = -2.0f * yb2;
            float mn[9];
            #pragma unroll
            for (int j = 0; j < 9; j++) mn[j] = 3.0e38f;
            const int cl = have ? cn : 0;
            #pragma unroll 2
            for (int k = s; k < cl; k += 8) {
                const float4 c = __ldg(&cp[k]);   // coalesced 128B/warp, L1-hot
                const float w0 = fmaf(n2y0, c.y, c.z);
                const float w1 = fmaf(n2y1, c.y, c.z);
                const float w2 = fmaf(n2y2, c.y, c.z);
                mn[0] = fminf(mn[0], fmaf(n2x0, c.x, w0));
                mn[1] = fminf(mn[1], fmaf(n2x1, c.x, w0));
                mn[2] = fminf(mn[2], fmaf(n2x2, c.x, w0));
                mn[3] = fminf(mn[3], fmaf(n2x0, c.x, w1));
                mn[4] = fminf(mn[4], fmaf(n2x1, c.x, w1));
                mn[5] = fminf(mn[5], fmaf(n2x2, c.x, w1));
                mn[6] = fminf(mn[6], fmaf(n2x0, c.x, w2));
                mn[7] = fminf(mn[7], fmaf(n2x1, c.x, w2));
                mn[8] = fminf(mn[8], fmaf(n2x2, c.x, w2));
            }
            #pragma unroll
            for (int j = 0; j < 9; j++) {     // reduce over the 8 slices
                float v = mn[j];
                v = fminf(v, __shfl_xor_sync(FULL, v, 1));
                v = fminf(v, __shfl_xor_sync(FULL, v, 2));
                v = fminf(v, __shfl_xor_sync(FULL, v, 4));
                mn[j] = v;
            }
            if (s == 0 && have) {
                const float x2[3] = {xa0 * xa0, xa1 * xa1, xa2 * xa2};
                const float y2[3] = {yb0 * yb0, yb1 * yb1, yb2 * yb2};
                float* o = out + (size_t)q * 9;
                #pragma unroll
                for (int j = 0; j < 9; j++) {
                    float d2 = mn[j] + x2[j % 3] + y2[j / 3];
                    o[j] = active ? 0.01f * sqrtf(fmaxf(d2, 0.0f)) : 0.0f;
                }
            }
        }
    } else {
        // ---- slow path: one warp per wrapped query, full candidate list ----
        __shared__ int s_soff[SEGS + 1];
        if (tid < SEGS) s_soff[tid + 1] = g_scnt[tid];
        if (tid == 0) s_soff[0] = 0;
        __syncthreads();
        if (tid == 0) {
            int a = 0;
            #pragma unroll
            for (int i = 0; i < SEGS; i++) { a += s_soff[i + 1]; s_soff[i + 1] = a; }
        }
        __syncthreads();
        const int total = s_soff[SEGS];
        const int wg = (b - TILES) * 16 + (tid >> 5);
        for (int si = wg; si < total; si += SLOW_BLOCKS * 16) {
            int seg = 0;
            #pragma unroll
            for (int i = 1; i < SEGS; i++) if (si >= s_soff[i]) seg = i;
            const int2 e = g_slow[seg][si - s_soff[seg]];
            const int q = e.x;
            const unsigned xy = (unsigned)e.y;
            const int x = (int)(xy & 0xffffu), y = (int)(xy >> 16);
            int xm = x - 1; if (xm < 0)      xm += GRIDW;
            int xp = x + 1; if (xp >= GRIDW) xp -= GRIDW;
            int ym = y - 1; if (ym < 0)      ym += GRIDW;
            int yp = y + 1; if (yp >= GRIDW) yp -= GRIDW;
            const float xa0 = (float)x,  xa1 = (float)xm, xa2 = (float)xp;
            const float yb0 = (float)y,  yb1 = (float)yp, yb2 = (float)ym;
            const float n2x0 = -2.0f * xa0, n2x1 = -2.0f * xa1, n2x2 = -2.0f * xa2;
            const float n2y0 = -2.0f * yb0, n2y1 = -2.0f * yb1, n2y2 = -2.0f * yb2;
            float mn[9];
            #pragma unroll
            for (int j = 0; j < 9; j++) mn[j] = 3.0e38f;
            for (int k = lane; k < cc; k += 32) {
                const float4 c = __ldg(&g_cand[k]);
                const float w0 = fmaf(n2y0, c.y, c.z);
                const float w1 = fmaf(n2y1, c.y, c.z);
                const float w2 = fmaf(n2y2, c.y, c.z);
                mn[0] = fminf(mn[0], fmaf(n2x0, c.x, w0));
                mn[1] = fminf(mn[1], fmaf(n2x1, c.x, w0));
                mn[2] = fminf(mn[2], fmaf(n2x2, c.x, w0));
                mn[3] = fminf(mn[3], fmaf(n2x0, c.x, w1));
                mn[4] = fminf(mn[4], fmaf(n2x1, c.x, w1));
                mn[5] = fminf(mn[5], fmaf(n2x2, c.x, w1));
                mn[6] = fminf(mn[6], fmaf(n2x0, c.x, w2));
                mn[7] = fminf(mn[7], fmaf(n2x1, c.x, w2));
                mn[8] = fminf(mn[8], fmaf(n2x2, c.x, w2));
            }
            #pragma unroll
            for (int j = 0; j < 9; j++) {
                float v = mn[j];
                #pragma unroll
                for (int o = 16; o; o >>= 1) v = fminf(v, __shfl_xor_sync(FULL, v, o));
                mn[j] = v;
            }
            if (lane == 0) {
                const float x2[3] = {xa0 * xa0, xa1 * xa1, xa2 * xa2};
                const float y2[3] = {yb0 * yb0, yb1 * yb1, yb2 * yb2};
                float* o = out + (size_t)q * 9;
                #pragma unroll
                for (int j = 0; j < 9; j++) {
                    float d2 = mn[j] + x2[j % 3] + y2[j / 3];
                    o[j] = active ? 0.01f * sqrtf(fmaxf(d2, 0.0f)) : 0.0f;
                }
            }
        }
    }
}

extern "C" void kernel_launch(void* const* d_in, const int* in_sizes, int n_in,
                              void* d_out, int out_size) {
    const int*   li  = (const int*)d_in[0];
    const int*   ra  = (const int*)d_in[1];
    const float* pts = (const float*)d_in[2];
    const int*   vox = (const int*)d_in[3];
    float* out = (float*)d_out;
    k1_prep<<<SEGS + 1 + TILES, 256>>>(li, ra, pts, vox);
    k2_main<<<TILES + SLOW_BLOCKS, 512>>>(out);
}

// round 7
// speedup vs baseline: 1.1358x; 1.1358x over previous
#include <cuda_runtime.h>
#include <math.h>

#define N_LI 8192
#define N_RA 2048
#define N_Q  (N_LI + N_RA)
#define M_PTS 2048
#define GRIDW 513
#define TSH 5                     // 32-wide tiles
#define TILES 256
#define TPB 512
#define NSLOW_BLK 8
#define SLOWSEG (N_Q / NSLOW_BLK) // 1280
#define SLOWIT ((SLOWSEG + TPB - 1) / TPB)   // 3 (round-6 bug: was 2)
#define QCAP_T 640                // per-tile query cap (mean ~40)
#define SQCAP 96                  // per-slow-block wrapped cap (mean ~5)
#define TWO_R_SLACK 47.6691f      // 2 * 16.5*sqrt(2) + 1.0 slack

// Fully fused: every block is self-contained (reads only the raw inputs,
// writes only its own outputs). No device-global scratch, no second launch.
__global__ __launch_bounds__(TPB, 2) void gauss_map_fused(
    const int* __restrict__ li, const int* __restrict__ ra,
    const float* __restrict__ pts, const int* __restrict__ vox,
    float* __restrict__ out)
{
    __shared__ __align__(16) float4 s_c[M_PTS];   // 32KB candidate list
    __shared__ int2  s_q[QCAP_T];                 // this block's queries {q, x|y<<16}
    __shared__ float s_mred[16];
    __shared__ int   s_cred[16];
    __shared__ float s_thr;
    __shared__ int   s_nc, s_nq, s_tot;

    const int b = blockIdx.x, tid = threadIdx.x, lane = tid & 31, w = tid >> 5;
    const unsigned FULL = 0xffffffffu;
    const bool is_tile = b < TILES;
    if (tid == 0) { s_nc = 0; s_nq = 0; }

    // ---- pass 1 over points: dynamic count (+ tile: Umin vs tile ref) ----
    const float refx = is_tile ? (float)((b & 15) << TSH) + 15.5f : 0.0f;
    const float refy = is_tile ? (float)((b >> 4) << TSH) + 15.5f : 0.0f;
    float mv = 3.0e38f;
    int cntd = 0;
    #pragma unroll
    for (int it = 0; it < M_PTS / TPB; it++) {
        int i = it * TPB + tid;
        if (fabsf(pts[i * 5 + 4]) > 0.1f) {
            cntd++;
            if (is_tile) {
                float dx = (float)vox[i * 3 + 1] - refx;
                float dy = (float)vox[i * 3 + 2] - refy;
                mv = fminf(mv, fmaf(dx, dx, dy * dy));
            }
        }
    }
    #pragma unroll
    for (int o = 16; o; o >>= 1) {
        mv = fminf(mv, __shfl_xor_sync(FULL, mv, o));
        cntd += __shfl_xor_sync(FULL, cntd, o);
    }
    if (lane == 0) { s_mred[w] = mv; s_cred[w] = cntd; }
    __syncthreads();
    if (tid == 0) {
        float m = s_mred[0]; int c = s_cred[0];
        #pragma unroll
        for (int i = 1; i < 16; i++) { m = fminf(m, s_mred[i]); c += s_cred[i]; }
        s_tot = c;
        float u = sqrtf(m) + TWO_R_SLACK;    // keep iff d(ref,c) <= sqrt(Umin)+2R+1
        s_thr = u * u;
    }
    __syncthreads();
    const bool active = s_tot > 1;           // reference: use = sum(dy_mask) > 1
    const float thr = is_tile ? s_thr : 3.9e38f;   // slow blocks keep everything

    // ---- pass 2 over points (L1-hot): ballot-compact kept candidates ----
    if (active) {
        #pragma unroll
        for (int it = 0; it < M_PTS / TPB; it++) {
            int i = it * TPB + tid;
            bool keep = false; float px = 0.f, py = 0.f;
            if (fabsf(pts[i * 5 + 4]) > 0.1f) {
                px = (float)vox[i * 3 + 1];
                py = (float)vox[i * 3 + 2];
                float dx = px - refx, dy = py - refy;
                keep = fmaf(dx, dx, dy * dy) <= thr;
            }
            unsigned m = __ballot_sync(FULL, keep);
            int base;
            if (lane == 0) base = atomicAdd(&s_nc, __popc(m));
            base = __shfl_sync(FULL, base, 0);
            if (keep)
                s_c[base + __popc(m & ((1u << lane) - 1u))] =
                    make_float4(px, py, fmaf(px, px, py * py), 0.0f);
        }
    }

    // ---- query scan: collect this block's queries ----
    if (is_tile) {
        #pragma unroll
        for (int it = 0; it < N_Q / TPB; it++) {   // 10240/512 = 20, exact
            int q = it * TPB + tid;
            const int* p = (q < N_LI) ? (li + 2 * q) : (ra + 2 * (q - N_LI));
            int x = p[0], y = p[1];
            bool mine = (x != 0) && (y != 0) &&
                        ((((y >> TSH) << 4) | (x >> TSH)) == b);
            unsigned mm = __ballot_sync(FULL, mine);
            int base;
            if (lane == 0) base = atomicAdd(&s_nq, __popc(mm));
            base = __shfl_sync(FULL, base, 0);
            if (mine) {
                int idx = base + __popc(mm & ((1u << lane) - 1u));
                if (idx < QCAP_T) s_q[idx] = make_int2(q, x | (y << 16));
            }
        }
    } else {
        const int sb = b - TILES;
        #pragma unroll
        for (int it = 0; it < SLOWIT; it++) {      // 3 iters; guard covers 1280
            int r = it * TPB + tid;
            if (r < SLOWSEG) {
                int q = sb * SLOWSEG + r;
                const int* p = (q < N_LI) ? (li + 2 * q) : (ra + 2 * (q - N_LI));
                int x = p[0], y = p[1];
                if (x == 0 || y == 0) {
                    int idx = atomicAdd(&s_nq, 1);
                    if (idx < SQCAP) s_q[idx] = make_int2(q, x | (y << 16));
                }
            }
        }
    }
    __syncthreads();
    const int qn = min(s_nq, is_tile ? QCAP_T : SQCAP);
    if (qn == 0) return;
    const int cn = active ? s_nc : 0;

    if (is_tile) {
        // ---- 8-sliced eval: 64 query slots x 8 candidate slices ----
        const int s = tid & 7, qslot = tid >> 3;
        for (int q0 = 0; q0 < qn; q0 += 64) {
            const int qi = q0 + qslot;
            const bool have = qi < qn;
            int2 e = have ? s_q[qi] : make_int2(0, 0);
            const unsigned xy = (unsigned)e.y;
            const int x = (int)(xy & 0xffffu), y = (int)(xy >> 16);
            // INDEX_SHIFT: dim0 {0,-1,+1} (a=j%3), dim1 {0,+1,-1} (b=j/3); no wrap
            const float xa0 = (float)x, xa1 = (float)(x - 1), xa2 = (float)(x + 1);
            const float yb0 = (float)y, yb1 = (float)(y + 1), yb2 = (float)(y - 1);
            const float n2x0 = -2.0f * xa0, n2x1 = -2.0f * xa1, n2x2 = -2.0f * xa2;
            const float n2y0 = -2.0f * yb0, n2y1 = -2.0f * yb1, n2y2 = -2.0f * yb2;
            float mn[9];
            #pragma unroll
            for (int j = 0; j < 9; j++) mn[j] = 3.0e38f;
            const int cl = have ? cn : 0;
            #pragma unroll 2
            for (int k = s; k < cl; k += 8) {
                const float4 c = s_c[k];                 // conflict-free LDS.128
                const float w0 = fmaf(n2y0, c.y, c.z);
                const float w1 = fmaf(n2y1, c.y, c.z);
                const float w2 = fmaf(n2y2, c.y, c.z);
                mn[0] = fminf(mn[0], fmaf(n2x0, c.x, w0));
                mn[1] = fminf(mn[1], fmaf(n2x1, c.x, w0));
                mn[2] = fminf(mn[2], fmaf(n2x2, c.x, w0));
                mn[3] = fminf(mn[3], fmaf(n2x0, c.x, w1));
                mn[4] = fminf(mn[4], fmaf(n2x1, c.x, w1));
                mn[5] = fminf(mn[5], fmaf(n2x2, c.x, w1));
                mn[6] = fminf(mn[6], fmaf(n2x0, c.x, w2));
                mn[7] = fminf(mn[7], fmaf(n2x1, c.x, w2));
                mn[8] = fminf(mn[8], fmaf(n2x2, c.x, w2));
            }
            #pragma unroll
            for (int j = 0; j < 9; j++) {                // reduce over 8 slices
                float v = mn[j];
                v = fminf(v, __shfl_xor_sync(FULL, v, 1));
                v = fminf(v, __shfl_xor_sync(FULL, v, 2));
                v = fminf(v, __shfl_xor_sync(FULL, v, 4));
                mn[j] = v;
            }
            if (s == 0 && have) {
                const float x2[3] = {xa0 * xa0, xa1 * xa1, xa2 * xa2};
                const float y2[3] = {yb0 * yb0, yb1 * yb1, yb2 * yb2};
                float* o = out + (size_t)e.x * 9;
                #pragma unroll
                for (int j = 0; j < 9; j++) {
                    float d2 = mn[j] + x2[j % 3] + y2[j / 3];
                    o[j] = active ? 0.01f * sqrtf(fmaxf(d2, 0.0f)) : 0.0f;
                }
            }
        }
    } else {
        // ---- slow path: one warp per wrapped query, full candidate list ----
        for (int si = w; si < qn; si += 16) {
            const int2 e = s_q[si];
            const unsigned xy = (unsigned)e.y;
            const int x = (int)(xy & 0xffffu), y = (int)(xy >> 16);
            int xm = x - 1; if (xm < 0)      xm += GRIDW;
            int xp = x + 1; if (xp >= GRIDW) xp -= GRIDW;
            int ym = y - 1; if (ym < 0)      ym += GRIDW;
            int yp = y + 1; if (yp >= GRIDW) yp -= GRIDW;
            const float xa0 = (float)x,  xa1 = (float)xm, xa2 = (float)xp;
            const float yb0 = (float)y,  yb1 = (float)yp, yb2 = (float)ym;
            const float n2x0 = -2.0f * xa0, n2x1 = -2.0f * xa1, n2x2 = -2.0f * xa2;
            const float n2y0 = -2.0f * yb0, n2y1 = -2.0f * yb1, n2y2 = -2.0f * yb2;
            float mn[9];
            #pragma unroll
            for (int j = 0; j < 9; j++) mn[j] = 3.0e38f;
            for (int k = lane; k < cn; k += 32) {
                const float4 c = s_c[k];
                const float w0 = fmaf(n2y0, c.y, c.z);
                const float w1 = fmaf(n2y1, c.y, c.z);
                const float w2 = fmaf(n2y2, c.y, c.z);
                mn[0] = fminf(mn[0], fmaf(n2x0, c.x, w0));
                mn[1] = fminf(mn[1], fmaf(n2x1, c.x, w0));
                mn[2] = fminf(mn[2], fmaf(n2x2, c.x, w0));
                mn[3] = fminf(mn[3], fmaf(n2x0, c.x, w1));
                mn[4] = fminf(mn[4], fmaf(n2x1, c.x, w1));
                mn[5] = fminf(mn[5], fmaf(n2x2, c.x, w1));
                mn[6] = fminf(mn[6], fmaf(n2x0, c.x, w2));
                mn[7] = fminf(mn[7], fmaf(n2x1, c.x, w2));
                mn[8] = fminf(mn[8], fmaf(n2x2, c.x, w2));
            }
            #pragma unroll
            for (int j = 0; j < 9; j++) {
                float v = mn[j];
                #pragma unroll
                for (int o = 16; o; o >>= 1) v = fminf(v, __shfl_xor_sync(FULL, v, o));
                mn[j] = v;
            }
            if (lane == 0) {
                const float x2[3] = {xa0 * xa0, xa1 * xa1, xa2 * xa2};
                const float y2[3] = {yb0 * yb0, yb1 * yb1, yb2 * yb2};
                float* o = out + (size_t)e.x * 9;
                #pragma unroll
                for (int j = 0; j < 9; j++) {
                    float d2 = mn[j] + x2[j % 3] + y2[j / 3];
                    o[j] = active ? 0.01f * sqrtf(fmaxf(d2, 0.0f)) : 0.0f;
                }
            }
        }
    }
}

extern "C" void kernel_launch(void* const* d_in, const int* in_sizes, int n_in,
                              void* d_out, int out_size) {
    const int*   li  = (const int*)d_in[0];
    const int*   ra  = (const int*)d_in[1];
    const float* pts = (const float*)d_in[2];
    const int*   vox = (const int*)d_in[3];
    float* out = (float*)d_out;
    gauss_map_fused<<<TILES + NSLOW_BLK, TPB>>>(li, ra, pts, vox, out);
}

// round 8
// speedup vs baseline: 1.5731x; 1.3851x over previous
#include <cuda_runtime.h>
#include <math.h>

#define N_LI 8192
#define N_RA 2048
#define N_Q  (N_LI + N_RA)
#define M_PTS 2048
#define GRIDW 513
#define TSH 5                     // 32-wide tiles
#define TILES 256
#define TPB 512
#define PITERS (M_PTS / TPB)      // 4
#define NSLOW_BLK 8
#define SLOWSEG (N_Q / NSLOW_BLK) // 1280
#define SLOWIT ((SLOWSEG + TPB - 1) / TPB)   // 3
#define QCAP_T 640                // per-tile query cap (mean ~40)
#define SQCAP 96                  // per-slow-block wrapped cap (mean ~5)
#define TWO_R_SLACK 47.6691f      // 2 * 16.5*sqrt(2) + 1.0 slack
#define FINF __int_as_float(0x7f800000)

// Fully fused, scan-lean: every block self-contained; no ballot-compaction
// (order in s_q/s_c is irrelevant to the min), int2 query loads, point data
// cached in registers between the threshold pass and the compaction pass.
__global__ __launch_bounds__(TPB, 2) void gauss_map_fused(
    const int* __restrict__ li, const int* __restrict__ ra,
    const float* __restrict__ pts, const int* __restrict__ vox,
    float* __restrict__ out)
{
    __shared__ __align__(16) float4 s_c[M_PTS];   // 32KB candidate list
    __shared__ int2  s_q[QCAP_T];                 // this block's queries {q, x|y<<16}
    __shared__ float s_mred[16];
    __shared__ int   s_cred[16];
    __shared__ int   s_nc, s_nq;

    const int b = blockIdx.x, tid = threadIdx.x, lane = tid & 31, w = tid >> 5;
    const unsigned FULL = 0xffffffffu;
    const bool is_tile = b < TILES;
    if (tid == 0) { s_nc = 0; s_nq = 0; }

    // ---- single pass over points: d2 vs tile ref cached in registers ----
    const float refx = is_tile ? (float)((b & 15) << TSH) + 15.5f : 0.0f;
    const float refy = is_tile ? (float)((b >> 4) << TSH) + 15.5f : 0.0f;
    float pxr[PITERS], pyr[PITERS], d2r[PITERS];
    float mv = FINF;
    int cntw = 0;
    #pragma unroll
    for (int it = 0; it < PITERS; it++) {
        int i = it * TPB + tid;
        bool pass = fabsf(pts[i * 5 + 4]) > 0.1f;
        cntw += __popc(__ballot_sync(FULL, pass));   // warp count, no reduce needed
        float px = 0.f, py = 0.f, d2 = FINF;
        if (pass) {
            px = (float)vox[i * 3 + 1];
            py = (float)vox[i * 3 + 2];
            float dx = px - refx, dy = py - refy;
            d2 = fmaf(dx, dx, dy * dy);
        }
        pxr[it] = px; pyr[it] = py; d2r[it] = d2;
        mv = fminf(mv, d2);
    }
    #pragma unroll
    for (int o = 16; o; o >>= 1) mv = fminf(mv, __shfl_xor_sync(FULL, mv, o));
    if (lane == 0) { s_mred[w] = mv; s_cred[w] = cntw; }
    __syncthreads();

    // all threads fold the 16 warp partials locally (cheaper than a 2nd sync)
    float m = s_mred[0]; int tot = s_cred[0];
    #pragma unroll
    for (int i = 1; i < 16; i++) { m = fminf(m, s_mred[i]); tot += s_cred[i]; }
    const bool active = tot > 1;             // reference: use = sum(dy_mask) > 1
    float thr = 3.9e38f;                     // slow blocks: keep all dynamic pts
    if (is_tile) {
        float u = sqrtf(m) + TWO_R_SLACK;    // keep iff d(ref,c) <= sqrt(Umin)+2R+1
        thr = u * u;
    }

    // ---- register-only compaction pass (rare shared atomic, no ballot) ----
    if (active) {
        #pragma unroll
        for (int it = 0; it < PITERS; it++) {
            if (d2r[it] <= thr) {            // INF for non-dynamic never passes
                int idx = atomicAdd(&s_nc, 1);
                float px = pxr[it], py = pyr[it];
                s_c[idx] = make_float4(px, py, fmaf(px, px, py * py), 0.0f);
            }
        }
    }

    // ---- query scan: int2 loads, direct rare atomics ----
    if (is_tile) {
        const int2* __restrict__ li2 = (const int2*)li;
        const int2* __restrict__ ra2 = (const int2*)ra;
        #pragma unroll
        for (int it = 0; it < N_LI / TPB; it++) {    // 16 iters
            int q = it * TPB + tid;
            int2 e = li2[q];
            int t = ((e.y >> TSH) << 4) | (e.x >> TSH);
            if (t == b && e.x != 0 && e.y != 0) {
                int idx = atomicAdd(&s_nq, 1);
                if (idx < QCAP_T) s_q[idx] = make_int2(q, e.x | (e.y << 16));
            }
        }
        #pragma unroll
        for (int it = 0; it < N_RA / TPB; it++) {    // 4 iters
            int r = it * TPB + tid;
            int2 e = ra2[r];
            int t = ((e.y >> TSH) << 4) | (e.x >> TSH);
            if (t == b && e.x != 0 && e.y != 0) {
                int idx = atomicAdd(&s_nq, 1);
                if (idx < QCAP_T) s_q[idx] = make_int2(N_LI + r, e.x | (e.y << 16));
            }
        }
    } else {
        const int sb = b - TILES;
        #pragma unroll
        for (int it = 0; it < SLOWIT; it++) {
            int r = it * TPB + tid;
            if (r < SLOWSEG) {
                int q = sb * SLOWSEG + r;
                const int* p = (q < N_LI) ? (li + 2 * q) : (ra + 2 * (q - N_LI));
                int x = p[0], y = p[1];
                if (x == 0 || y == 0) {
                    int idx = atomicAdd(&s_nq, 1);
                    if (idx < SQCAP) s_q[idx] = make_int2(q, x | (y << 16));
                }
            }
        }
    }
    __syncthreads();
    const int qn = min(s_nq, is_tile ? QCAP_T : SQCAP);
    if (qn == 0) return;
    const int cn = active ? s_nc : 0;

    if (is_tile) {
        // ---- 8-sliced eval: 64 query slots x 8 candidate slices ----
        const int s = tid & 7, qslot = tid >> 3;
        for (int q0 = 0; q0 < qn; q0 += 64) {
            const int qi = q0 + qslot;
            const bool have = qi < qn;
            int2 e = have ? s_q[qi] : make_int2(0, 0);
            const unsigned xy = (unsigned)e.y;
            const int x = (int)(xy & 0xffffu), y = (int)(xy >> 16);
            // INDEX_SHIFT: dim0 {0,-1,+1} (a=j%3), dim1 {0,+1,-1} (b=j/3); no wrap
            const float xa0 = (float)x, xa1 = (float)(x - 1), xa2 = (float)(x + 1);
            const float yb0 = (float)y, yb1 = (float)(y + 1), yb2 = (float)(y - 1);
            const float n2x0 = -2.0f * xa0, n2x1 = -2.0f * xa1, n2x2 = -2.0f * xa2;
            const float n2y0 = -2.0f * yb0, n2y1 = -2.0f * yb1, n2y2 = -2.0f * yb2;
            float mn[9];
            #pragma unroll
            for (int j = 0; j < 9; j++) mn[j] = 3.0e38f;
            const int cl = have ? cn : 0;
            #pragma unroll 2
            for (int k = s; k < cl; k += 8) {
                const float4 c = s_c[k];                 // conflict-free LDS.128
                const float w0 = fmaf(n2y0, c.y, c.z);
                const float w1 = fmaf(n2y1, c.y, c.z);
                const float w2 = fmaf(n2y2, c.y, c.z);
                mn[0] = fminf(mn[0], fmaf(n2x0, c.x, w0));
                mn[1] = fminf(mn[1], fmaf(n2x1, c.x, w0));
                mn[2] = fminf(mn[2], fmaf(n2x2, c.x, w0));
                mn[3] = fminf(mn[3], fmaf(n2x0, c.x, w1));
                mn[4] = fminf(mn[4], fmaf(n2x1, c.x, w1));
                mn[5] = fminf(mn[5], fmaf(n2x2, c.x, w1));
                mn[6] = fminf(mn[6], fmaf(n2x0, c.x, w2));
                mn[7] = fminf(mn[7], fmaf(n2x1, c.x, w2));
                mn[8] = fminf(mn[8], fmaf(n2x2, c.x, w2));
            }
            #pragma unroll
            for (int j = 0; j < 9; j++) {                // reduce over 8 slices
                float v = mn[j];
                v = fminf(v, __shfl_xor_sync(FULL, v, 1));
                v = fminf(v, __shfl_xor_sync(FULL, v, 2));
                v = fminf(v, __shfl_xor_sync(FULL, v, 4));
                mn[j] = v;
            }
            if (s == 0 && have) {
                const float x2[3] = {xa0 * xa0, xa1 * xa1, xa2 * xa2};
                const float y2[3] = {yb0 * yb0, yb1 * yb1, yb2 * yb2};
                float* o = out + (size_t)e.x * 9;
                #pragma unroll
                for (int j = 0; j < 9; j++) {
                    float d2 = mn[j] + x2[j % 3] + y2[j / 3];
                    o[j] = active ? 0.01f * sqrtf(fmaxf(d2, 0.0f)) : 0.0f;
                }
            }
        }
    } else {
        // ---- slow path: one warp per wrapped query, full candidate list ----
        for (int si = w; si < qn; si += 16) {
            const int2 e = s_q[si];
            const unsigned xy = (unsigned)e.y;
            const int x = (int)(xy & 0xffffu), y = (int)(xy >> 16);
            int xm = x - 1; if (xm < 0)      xm += GRIDW;
            int xp = x + 1; if (xp >= GRIDW) xp -= GRIDW;
            int ym = y - 1; if (ym < 0)      ym += GRIDW;
            int yp = y + 1; if (yp >= GRIDW) yp -= GRIDW;
            const float xa0 = (float)x,  xa1 = (float)xm, xa2 = (float)xp;
            const float yb0 = (float)y,  yb1 = (float)yp, yb2 = (float)ym;
            const float n2x0 = -2.0f * xa0, n2x1 = -2.0f * xa1, n2x2 = -2.0f * xa2;
            const float n2y0 = -2.0f * yb0, n2y1 = -2.0f * yb1, n2y2 = -2.0f * yb2;
            float mn[9];
            #pragma unroll
            for (int j = 0; j < 9; j++) mn[j] = 3.0e38f;
            for (int k = lane; k < cn; k += 32) {
                const float4 c = s_c[k];
                const float w0 = fmaf(n2y0, c.y, c.z);
                const float w1 = fmaf(n2y1, c.y, c.z);
                const float w2 = fmaf(n2y2, c.y, c.z);
                mn[0] = fminf(mn[0], fmaf(n2x0, c.x, w0));
                mn[1] = fminf(mn[1], fmaf(n2x1, c.x, w0));
                mn[2] = fminf(mn[2], fmaf(n2x2, c.x, w0));
                mn[3] = fminf(mn[3], fmaf(n2x0, c.x, w1));
                mn[4] = fminf(mn[4], fmaf(n2x1, c.x, w1));
                mn[5] = fminf(mn[5], fmaf(n2x2, c.x, w1));
                mn[6] = fminf(mn[6], fmaf(n2x0, c.x, w2));
                mn[7] = fminf(mn[7], fmaf(n2x1, c.x, w2));
                mn[8] = fminf(mn[8], fmaf(n2x2, c.x, w2));
            }
            #pragma unroll
            for (int j = 0; j < 9; j++) {
                float v = mn[j];
                #pragma unroll
                for (int o = 16; o; o >>= 1) v = fminf(v, __shfl_xor_sync(FULL, v, o));
                mn[j] = v;
            }
            if (lane == 0) {
                const float x2[3] = {xa0 * xa0, xa1 * xa1, xa2 * xa2};
                const float y2[3] = {yb0 * yb0, yb1 * yb1, yb2 * yb2};
                float* o = out + (size_t)e.x * 9;
                #pragma unroll
                for (int j = 0; j < 9; j++) {
                    float d2 = mn[j] + x2[j % 3] + y2[j / 3];
                    o[j] = active ? 0.01f * sqrtf(fmaxf(d2, 0.0f)) : 0.0f;
                }
            }
        }
    }
}

extern "C" void kernel_launch(void* const* d_in, const int* in_sizes, int n_in,
                              void* d_out, int out_size) {
    const int*   li  = (const int*)d_in[0];
    const int*   ra  = (const int*)d_in[1];
    const float* pts = (const float*)d_in[2];
    const int*   vox = (const int*)d_in[3];
    float* out = (float*)d_out;
    gauss_map_fused<<<TILES + NSLOW_BLK, TPB>>>(li, ra, pts, vox, out);
}